// round 1
// baseline (speedup 1.0000x reference)
#include <cuda_runtime.h>
#include <cuda_bf16.h>
#include <math.h>

#define T_TOKENS 4096
#define D_HID    2048
#define HE       1024
#define NEXP     8
#define VOCAB    100000
#define TPE      12500   // VOCAB / NEXP

#define BM 64
#define BN 64
#define BK 16

// ---- device scratch (no allocs allowed) ----
__device__ int   d_counts[NEXP];
__device__ int   d_offsets[NEXP];
__device__ int   d_cursor[NEXP];
__device__ int   d_perm[T_TOKENS];
__device__ float d_hbuf[(size_t)T_TOKENS * HE];   // 16 MB intermediate h (permuted row order)

// ============================================================================
// Routing: single block. Detect token dtype (int32 vs int64), compute expert
// per token, count, scan, scatter into per-expert-contiguous perm[].
// ============================================================================
__global__ void route_kernel(const void* __restrict__ tok_raw) {
    __shared__ int s_is64;
    __shared__ int s_counts[NEXP];
    int tid = threadIdx.x;
    if (tid < NEXP) s_counts[tid] = 0;
    if (tid == 0) {
        // If int64 little-endian values (< 2^31), all odd 32-bit words are 0.
        // If int32 tokens, odd words are random tokens in [0,100000) — ~never all 0.
        const int* w = (const int*)tok_raw;
        int allz = 1;
        for (int i = 1; i < 512; i += 2) {
            if (w[i] != 0) { allz = 0; break; }
        }
        s_is64 = allz;
    }
    __syncthreads();
    const int is64 = s_is64;

    int eid[T_TOKENS / 256];
#pragma unroll
    for (int it = 0; it < T_TOKENS / 256; it++) {
        int t = tid + it * 256;
        long long v;
        if (is64) v = ((const long long*)tok_raw)[t];
        else      v = (long long)((const int*)tok_raw)[t];
        if (v < 0) v = 0;
        if (v > VOCAB - 1) v = VOCAB - 1;
        int e = (int)(v / TPE);
        if (e > NEXP - 1) e = NEXP - 1;
        eid[it] = e;
        atomicAdd(&s_counts[e], 1);
    }
    __syncthreads();
    if (tid == 0) {
        int off = 0;
        for (int e = 0; e < NEXP; e++) {
            d_counts[e]  = s_counts[e];
            d_offsets[e] = off;
            d_cursor[e]  = off;
            off += s_counts[e];
        }
    }
    __syncthreads();
#pragma unroll
    for (int it = 0; it < T_TOKENS / 256; it++) {
        int t   = tid + it * 256;
        int pos = atomicAdd(&d_cursor[eid[it]], 1);
        d_perm[pos] = t;
    }
}

// ============================================================================
// GEMM1: per expert, gathered rows of x [cnt, 2048] x (Wg, Wu) [2048, 1024]
// -> h = silu(g) * u, stored to d_hbuf in permuted (expert-contiguous) order.
// grid = (HE/BN, T_TOKENS/BM, NEXP); blocks past counts[e] exit early.
// ============================================================================
__global__ __launch_bounds__(256) void gemm1_kernel(
    const float* __restrict__ x,
    const float* __restrict__ Wg,
    const float* __restrict__ Wu)
{
    const int e   = blockIdx.z;
    const int cnt = d_counts[e];
    const int row0 = blockIdx.y * BM;
    if (row0 >= cnt) return;
    const int off = d_offsets[e];
    const int n0  = blockIdx.x * BN;

    __shared__ float As[BK][BM];
    __shared__ float Bg[BK][BN];
    __shared__ float Bu[BK][BN];

    const int tid = threadIdx.x;

    // A loader mapping: each thread loads a float4 along k for one row
    const int am   = tid >> 2;            // 0..63 row within tile
    const int aq   = (tid & 3) * 4;       // k offset 0/4/8/12
    const int arow = row0 + am;
    const int token = (arow < cnt) ? d_perm[off + arow] : d_perm[off]; // safe dup
    const float* x_base = x + (size_t)token * D_HID + aq;

    // B loader mapping: each thread loads a float4 along n for one k row
    const int bk = tid >> 4;              // 0..15
    const int bn = (tid & 15) * 4;        // 0..60
    const float* wg_base = Wg + (size_t)e * D_HID * HE + (size_t)bk * HE + n0 + bn;
    const float* wu_base = Wu + (size_t)e * D_HID * HE + (size_t)bk * HE + n0 + bn;

    // compute mapping: 16x16 threads, 4x4 microtile each
    const int tm = (tid >> 4) * 4;
    const int tn = (tid & 15) * 4;

    float accg[4][4] = {};
    float accu[4][4] = {};

    for (int k0 = 0; k0 < D_HID; k0 += BK) {
        float4 av = *(const float4*)(x_base + k0);
        float4 gv = *(const float4*)(wg_base + (size_t)k0 * HE);
        float4 uv = *(const float4*)(wu_base + (size_t)k0 * HE);
        As[aq + 0][am] = av.x;
        As[aq + 1][am] = av.y;
        As[aq + 2][am] = av.z;
        As[aq + 3][am] = av.w;
        *(float4*)&Bg[bk][bn] = gv;
        *(float4*)&Bu[bk][bn] = uv;
        __syncthreads();

#pragma unroll
        for (int kk = 0; kk < BK; kk++) {
            float a[4], bg[4], bu[4];
            *(float4*)a  = *(const float4*)&As[kk][tm];
            *(float4*)bg = *(const float4*)&Bg[kk][tn];
            *(float4*)bu = *(const float4*)&Bu[kk][tn];
#pragma unroll
            for (int i = 0; i < 4; i++)
#pragma unroll
                for (int j = 0; j < 4; j++) {
                    accg[i][j] = fmaf(a[i], bg[j], accg[i][j]);
                    accu[i][j] = fmaf(a[i], bu[j], accu[i][j]);
                }
        }
        __syncthreads();
    }

#pragma unroll
    for (int i = 0; i < 4; i++) {
        int r = row0 + tm + i;
        if (r < cnt) {
            float* hrow = d_hbuf + (size_t)(off + r) * HE + n0 + tn;
            float4 hv;
            float g, u;
            g = accg[i][0]; u = accu[i][0]; hv.x = (g / (1.0f + expf(-g))) * u;
            g = accg[i][1]; u = accu[i][1]; hv.y = (g / (1.0f + expf(-g))) * u;
            g = accg[i][2]; u = accu[i][2]; hv.z = (g / (1.0f + expf(-g))) * u;
            g = accg[i][3]; u = accu[i][3]; hv.w = (g / (1.0f + expf(-g))) * u;
            *(float4*)hrow = hv;
        }
    }
}

// ============================================================================
// GEMM2: per expert, h rows [cnt, 1024] x Wd [1024, 2048] -> scatter to out
// via perm. grid = (D_HID/BN, T_TOKENS/BM, NEXP).
// ============================================================================
__global__ __launch_bounds__(256) void gemm2_kernel(
    const float* __restrict__ Wd,
    float* __restrict__ out)
{
    const int e   = blockIdx.z;
    const int cnt = d_counts[e];
    const int row0 = blockIdx.y * BM;
    if (row0 >= cnt) return;
    const int off = d_offsets[e];
    const int n0  = blockIdx.x * BN;

    __shared__ float As[BK][BM];
    __shared__ float Bd[BK][BN];

    const int tid = threadIdx.x;

    const int am   = tid >> 2;
    const int aq   = (tid & 3) * 4;
    const int arow = row0 + am;
    const int hrow = (arow < cnt) ? (off + arow) : off;
    const float* h_base = d_hbuf + (size_t)hrow * HE + aq;

    const int bk = tid >> 4;
    const int bn = (tid & 15) * 4;
    const float* wd_base = Wd + (size_t)e * HE * D_HID + (size_t)bk * D_HID + n0 + bn;

    const int tm = (tid >> 4) * 4;
    const int tn = (tid & 15) * 4;

    float acc[4][4] = {};

    for (int k0 = 0; k0 < HE; k0 += BK) {
        float4 av = *(const float4*)(h_base + k0);
        float4 dv = *(const float4*)(wd_base + (size_t)k0 * D_HID);
        As[aq + 0][am] = av.x;
        As[aq + 1][am] = av.y;
        As[aq + 2][am] = av.z;
        As[aq + 3][am] = av.w;
        *(float4*)&Bd[bk][bn] = dv;
        __syncthreads();

#pragma unroll
        for (int kk = 0; kk < BK; kk++) {
            float a[4], b[4];
            *(float4*)a = *(const float4*)&As[kk][tm];
            *(float4*)b = *(const float4*)&Bd[kk][tn];
#pragma unroll
            for (int i = 0; i < 4; i++)
#pragma unroll
                for (int j = 0; j < 4; j++)
                    acc[i][j] = fmaf(a[i], b[j], acc[i][j]);
        }
        __syncthreads();
    }

#pragma unroll
    for (int i = 0; i < 4; i++) {
        int r = row0 + tm + i;
        if (r < cnt) {
            int token = d_perm[off + r];
            float* orow = out + (size_t)token * D_HID + n0 + tn;
            float4 ov;
            ov.x = acc[i][0]; ov.y = acc[i][1]; ov.z = acc[i][2]; ov.w = acc[i][3];
            *(float4*)orow = ov;
        }
    }
}

// ============================================================================
extern "C" void kernel_launch(void* const* d_in, const int* in_sizes, int n_in,
                              void* d_out, int out_size) {
    const float* x   = (const float*)d_in[0];   // [2,2048,2048] fp32
    const void*  tok = d_in[1];                 // [2,2048] int32 or int64 (sniffed)
    const float* Wg  = (const float*)d_in[2];   // [8,2048,1024]
    const float* Wu  = (const float*)d_in[3];   // [8,2048,1024]
    const float* Wd  = (const float*)d_in[4];   // [8,1024,2048]
    float* out = (float*)d_out;                 // [2,2048,2048]

    route_kernel<<<1, 256>>>(tok);

    dim3 g1(HE / BN,    T_TOKENS / BM, NEXP);
    gemm1_kernel<<<g1, 256>>>(x, Wg, Wu);

    dim3 g2(D_HID / BN, T_TOKENS / BM, NEXP);
    gemm2_kernel<<<g2, 256>>>(Wd, out);
}

// round 4
// speedup vs baseline: 1.1098x; 1.1098x over previous
#include <cuda_runtime.h>
#include <cstdint>

#define T_TOKENS 4096
#define D_HID    2048
#define HE       1024
#define NEXP     8
#define VOCAB    100000
#define TPE      12500

// ---- device scratch (no allocs allowed) ----
__device__ int   d_counts[NEXP];
__device__ int   d_offsets[NEXP];
__device__ int   d_cursor[NEXP];
__device__ int   d_perm[T_TOKENS];
__device__ float d_hbuf[(size_t)T_TOKENS * HE];   // 16 MB, permuted row order

// ============================ helpers ============================
__device__ __forceinline__ uint32_t f2tf(float f) {   // round-to-nearest tf32
    uint32_t r;
    asm("cvt.rna.tf32.f32 %0, %1;" : "=r"(r) : "f"(f));
    return r;
}

// m16n8k8 tf32 mma: D += A*B. acc 4 f32, a 4 b32, b 2 b32.
__device__ __forceinline__ void mma8(float* c, const uint4& a, const uint2& b) {
    asm volatile(
        "mma.sync.aligned.m16n8k8.row.col.f32.tf32.tf32.f32 "
        "{%0,%1,%2,%3},{%4,%5,%6,%7},{%8,%9},{%0,%1,%2,%3};"
        : "+f"(c[0]), "+f"(c[1]), "+f"(c[2]), "+f"(c[3])
        : "r"(a.x), "r"(a.y), "r"(a.z), "r"(a.w), "r"(b.x), "r"(b.y));
}

// fragment-order smem word indices
// A: [ks 4][mt 8][lane 32] x 4 regs, padded group stride 33 float4s
#define AFW(ks, mt, lane) ((((ks) * 8 + (mt)) * 33 + (lane)) * 4)
// B: [ks 4][nt 16][lane 32] x 2 regs
#define BFW(ks, nt, lane) ((((ks) * 16 + (nt)) * 32 + (lane)) * 2)
#define SA_WORDS (4 * 8 * 33 * 4)     // 4224
#define SB_WORDS (4 * 16 * 32 * 2)    // 4096

// ============================ routing ============================
__global__ void route_kernel(const void* __restrict__ tok_raw) {
    __shared__ int s_is64;
    __shared__ int s_counts[NEXP];
    int tid = threadIdx.x;
    if (tid < NEXP) s_counts[tid] = 0;
    if (tid == 0) {
        const int* w = (const int*)tok_raw;
        int allz = 1;
        for (int i = 1; i < 512; i += 2) if (w[i] != 0) { allz = 0; break; }
        s_is64 = allz;
    }
    __syncthreads();
    const int is64 = s_is64;
    int eid[T_TOKENS / 256];
#pragma unroll
    for (int it = 0; it < T_TOKENS / 256; it++) {
        int t = tid + it * 256;
        long long v = is64 ? ((const long long*)tok_raw)[t] : (long long)((const int*)tok_raw)[t];
        if (v < 0) v = 0;
        if (v > VOCAB - 1) v = VOCAB - 1;
        int ex = (int)(v / TPE);
        if (ex > NEXP - 1) ex = NEXP - 1;
        eid[it] = ex;
        atomicAdd(&s_counts[ex], 1);
    }
    __syncthreads();
    if (tid == 0) {
        int off = 0;
        for (int ex = 0; ex < NEXP; ex++) {
            d_counts[ex] = s_counts[ex];
            d_offsets[ex] = off;
            d_cursor[ex] = off;
            off += s_counts[ex];
        }
    }
    __syncthreads();
#pragma unroll
    for (int it = 0; it < T_TOKENS / 256; it++) {
        int t = tid + it * 256;
        int pos = atomicAdd(&d_cursor[eid[it]], 1);
        d_perm[pos] = t;
    }
}

// ============================================================================
// GEMM1: rows x[perm] (gathered) x [Wg|Wu interleaved] -> h = silu(g)*u
// block: 128 rows x 64 h-cols (128 combined cols: even=gate, odd=up)
// grid (HE/64=16, T/128=32, 8). K chunks of 32 over D_HID.
// ============================================================================
__global__ __launch_bounds__(256) void gemm1_kernel(
    const float* __restrict__ x,
    const float* __restrict__ Wg,
    const float* __restrict__ Wu)
{
    const int e = blockIdx.z;
    const int cnt = d_counts[e];
    const int row0 = blockIdx.y * 128;
    if (row0 >= cnt) return;
    const int off = d_offsets[e];
    const int bx = blockIdx.x;          // h col base = bx*64

    __shared__ uint32_t sA[SA_WORDS];
    __shared__ uint32_t sB[SB_WORDS];

    const int t = threadIdx.x, lane = t & 31, w = t >> 5;

    // --- A stage mapping: 2 threads/row, 4 float4s each along k ---
    const int ar = t & 127;
    const int jb = (t >> 7) * 4;        // j = jb..jb+3 (float4 index in 32-k chunk)
    int arr = row0 + ar; if (arr >= cnt) arr = cnt - 1;
    const float* pA = x + (size_t)d_perm[off + arr] * D_HID + jb * 4;
    const int mt = ar >> 4, mr = ar & 15;

    // --- B stage mapping: t<128 gate, t>=128 up; 4 float4s along k ---
    const int bsrc = t >> 7;            // 0=gate, 1=up
    const int bu = t & 127;
    const int n4 = bu >> 3;             // 0..15: source col group of 4
    const int kb = bu & 7;
    const int bc = kb & 3, bhf = kb >> 2;
    const float* pW = (bsrc ? Wu : Wg) + (size_t)e * D_HID * HE
                      + (size_t)kb * HE + bx * 64 + n4 * 4;

    const int wm = w & 1, wn = w >> 1;  // warp tile: 64 rows x 32 comb cols
    float acc[4][4][4] = {};
    float4 rA[4], rB[4];

#pragma unroll
    for (int jj = 0; jj < 4; jj++) rA[jj] = *(const float4*)(pA + jj * 4);
#pragma unroll
    for (int i = 0; i < 4; i++) rB[i] = *(const float4*)(pW + (size_t)(8 * i) * HE);

    for (int kc = 0; kc < D_HID / 32; kc++) {
        // ---- STS A (fragment order) ----
#pragma unroll
        for (int jj = 0; jj < 4; jj++) {
            int j = jb + jj, ks = j >> 1, hf = j & 1;
            int wb = AFW(ks, mt, (mr & 7) * 4) + hf * 2 + (mr >> 3);
            sA[wb + 0]  = f2tf(rA[jj].x);
            sA[wb + 4]  = f2tf(rA[jj].y);
            sA[wb + 8]  = f2tf(rA[jj].z);
            sA[wb + 12] = f2tf(rA[jj].w);
        }
        // ---- STS B (interleave gate even / up odd comb cols) ----
#pragma unroll
        for (int i = 0; i < 4; i++) {
            int base = BFW(i, n4, 4 * bsrc + bc) + bhf;   // e=0 lane = 4*bsrc+bc
            sB[base + 0]  = f2tf(rB[i].x);                // e: lane += 8e -> word += 16e
            sB[base + 16] = f2tf(rB[i].y);
            sB[base + 32] = f2tf(rB[i].z);
            sB[base + 48] = f2tf(rB[i].w);
        }
        __syncthreads();
        if (kc + 1 < D_HID / 32) {
#pragma unroll
            for (int jj = 0; jj < 4; jj++)
                rA[jj] = *(const float4*)(pA + (kc + 1) * 32 + jj * 4);
#pragma unroll
            for (int i = 0; i < 4; i++)
                rB[i] = *(const float4*)(pW + (size_t)((kc + 1) * 32 + 8 * i) * HE);
        }
        // ---- compute 4 k8-steps ----
#pragma unroll
        for (int ks = 0; ks < 4; ks++) {
            uint4 a[4]; uint2 b[4];
#pragma unroll
            for (int mi = 0; mi < 4; mi++)
                a[mi] = *(const uint4*)&sA[AFW(ks, wm * 4 + mi, lane)];
#pragma unroll
            for (int ni = 0; ni < 4; ni++)
                b[ni] = *(const uint2*)&sB[BFW(ks, wn * 4 + ni, lane)];
#pragma unroll
            for (int mi = 0; mi < 4; mi++)
#pragma unroll
                for (int ni = 0; ni < 4; ni++)
                    mma8(acc[mi][ni], a[mi], b[ni]);
        }
        __syncthreads();
    }

    // ---- epilogue: (d0,d1)=(gate,up) same element; silu in regs ----
#pragma unroll
    for (int mi = 0; mi < 4; mi++) {
        int rl = wm * 64 + mi * 16 + (lane >> 2);
        int r1 = row0 + rl, r2 = r1 + 8;
#pragma unroll
        for (int ni = 0; ni < 4; ni++) {
            int col = bx * 64 + wn * 16 + ni * 4 + (lane & 3);
            if (r1 < cnt) {
                float g = acc[mi][ni][0], u = acc[mi][ni][1];
                d_hbuf[(size_t)(off + r1) * HE + col] = g / (1.f + __expf(-g)) * u;
            }
            if (r2 < cnt) {
                float g = acc[mi][ni][2], u = acc[mi][ni][3];
                d_hbuf[(size_t)(off + r2) * HE + col] = g / (1.f + __expf(-g)) * u;
            }
        }
    }
}

// ============================================================================
// GEMM2: h rows (contiguous per expert) x Wd [1024,2048] -> scatter via perm
// block: 128 rows x 128 cols. grid (2048/128=16, 32, 8). K chunks of 32 over HE.
// ============================================================================
__global__ __launch_bounds__(256) void gemm2_kernel(
    const float* __restrict__ Wd,
    float* __restrict__ out)
{
    const int e = blockIdx.z;
    const int cnt = d_counts[e];
    const int row0 = blockIdx.y * 128;
    if (row0 >= cnt) return;
    const int off = d_offsets[e];
    const int bx = blockIdx.x;

    __shared__ uint32_t sA[SA_WORDS];
    __shared__ uint32_t sB[SB_WORDS];

    const int t = threadIdx.x, lane = t & 31, w = t >> 5;

    const int ar = t & 127;
    const int jb = (t >> 7) * 4;
    int hr = off + row0 + ar; if (hr > T_TOKENS - 1) hr = T_TOKENS - 1;
    const float* pA = d_hbuf + (size_t)hr * HE + jb * 4;
    const int mt = ar >> 4, mr = ar & 15;

    const int n4 = t >> 3;              // 0..31 (128 cols)
    const int kb = t & 7;
    const int bc = kb & 3, bhf = kb >> 2;
    const float* pW = Wd + (size_t)e * HE * D_HID + (size_t)kb * D_HID + bx * 128 + n4 * 4;

    const int wm = w & 1, wn = w >> 1;
    float acc[4][4][4] = {};
    float4 rA[4], rB[4];

#pragma unroll
    for (int jj = 0; jj < 4; jj++) rA[jj] = *(const float4*)(pA + jj * 4);
#pragma unroll
    for (int i = 0; i < 4; i++) rB[i] = *(const float4*)(pW + (size_t)(8 * i) * D_HID);

    for (int kc = 0; kc < HE / 32; kc++) {
#pragma unroll
        for (int jj = 0; jj < 4; jj++) {
            int j = jb + jj, ks = j >> 1, hf = j & 1;
            int wb = AFW(ks, mt, (mr & 7) * 4) + hf * 2 + (mr >> 3);
            sA[wb + 0]  = f2tf(rA[jj].x);
            sA[wb + 4]  = f2tf(rA[jj].y);
            sA[wb + 8]  = f2tf(rA[jj].z);
            sA[wb + 12] = f2tf(rA[jj].w);
        }
#pragma unroll
        for (int i = 0; i < 4; i++) {
            const float* vv = (const float*)&rB[i];
#pragma unroll
            for (int el = 0; el < 4; el++) {
                int n = n4 * 4 + el;
                int word = BFW(i, n >> 3, (n & 7) * 4 + bc) + bhf;
                sB[word] = f2tf(vv[el]);
            }
        }
        __syncthreads();
        if (kc + 1 < HE / 32) {
#pragma unroll
            for (int jj = 0; jj < 4; jj++)
                rA[jj] = *(const float4*)(pA + (kc + 1) * 32 + jj * 4);
#pragma unroll
            for (int i = 0; i < 4; i++)
                rB[i] = *(const float4*)(pW + (size_t)((kc + 1) * 32 + 8 * i) * D_HID);
        }
#pragma unroll
        for (int ks = 0; ks < 4; ks++) {
            uint4 a[4]; uint2 b[4];
#pragma unroll
            for (int mi = 0; mi < 4; mi++)
                a[mi] = *(const uint4*)&sA[AFW(ks, wm * 4 + mi, lane)];
#pragma unroll
            for (int ni = 0; ni < 4; ni++)
                b[ni] = *(const uint2*)&sB[BFW(ks, wn * 4 + ni, lane)];
#pragma unroll
            for (int mi = 0; mi < 4; mi++)
#pragma unroll
                for (int ni = 0; ni < 4; ni++)
                    mma8(acc[mi][ni], a[mi], b[ni]);
        }
        __syncthreads();
    }

#pragma unroll
    for (int mi = 0; mi < 4; mi++) {
        int rl = wm * 64 + mi * 16 + (lane >> 2);
        int r1 = row0 + rl, r2 = r1 + 8;
#pragma unroll
        for (int ni = 0; ni < 4; ni++) {
            int col = bx * 128 + wn * 32 + ni * 8 + 2 * (lane & 3);
            if (r1 < cnt) {
                float2 v; v.x = acc[mi][ni][0]; v.y = acc[mi][ni][1];
                *(float2*)(out + (size_t)d_perm[off + r1] * D_HID + col) = v;
            }
            if (r2 < cnt) {
                float2 v; v.x = acc[mi][ni][2]; v.y = acc[mi][ni][3];
                *(float2*)(out + (size_t)d_perm[off + r2] * D_HID + col) = v;
            }
        }
    }
}

// ============================ launch ============================
extern "C" void kernel_launch(void* const* d_in, const int* in_sizes, int n_in,
                              void* d_out, int out_size) {
    const float* x   = (const float*)d_in[0];
    const void*  tok = d_in[1];
    const float* Wg  = (const float*)d_in[2];
    const float* Wu  = (const float*)d_in[3];
    const float* Wd  = (const float*)d_in[4];
    float* out = (float*)d_out;

    route_kernel<<<1, 256>>>(tok);
    gemm1_kernel<<<dim3(HE / 64,   T_TOKENS / 128, NEXP), 256>>>(x, Wg, Wu);
    gemm2_kernel<<<dim3(D_HID / 128, T_TOKENS / 128, NEXP), 256>>>(Wd, out);
}

// round 5
// speedup vs baseline: 3.6258x; 3.2670x over previous
#include <cuda_runtime.h>
#include <cuda_fp16.h>
#include <cstdint>

#define T_TOKENS 4096
#define D_HID    2048
#define HE       1024
#define NEXP     8
#define VOCAB    100000
#define TPE      12500

// ---- device scratch (no allocs allowed) ----
__device__ int    d_counts[NEXP];
__device__ int    d_offsets[NEXP];
__device__ int    d_cursor[NEXP];
__device__ int    d_perm[T_TOKENS];
__device__ __half d_hbufh[(size_t)T_TOKENS * HE];   // 8 MB, permuted rows, fp16

// ============================ PTX helpers ============================
__device__ __forceinline__ uint32_t smem_u32(const void* p) {
    uint32_t a;
    asm("{ .reg .u64 t; cvta.to.shared.u64 t, %1; cvt.u32.u64 %0, t; }" : "=r"(a) : "l"(p));
    return a;
}
// m16n8k16 fp16 mma, fp32 accum
__device__ __forceinline__ void mma16(float* c, const uint4& a, const uint2& b) {
    asm volatile(
        "mma.sync.aligned.m16n8k16.row.col.f32.f16.f16.f32 "
        "{%0,%1,%2,%3},{%4,%5,%6,%7},{%8,%9},{%0,%1,%2,%3};"
        : "+f"(c[0]), "+f"(c[1]), "+f"(c[2]), "+f"(c[3])
        : "r"(a.x), "r"(a.y), "r"(a.z), "r"(a.w), "r"(b.x), "r"(b.y));
}
#define LDMX4(v, addr)                                                       \
    asm volatile("ldmatrix.sync.aligned.m8n8.x4.shared.b16 {%0,%1,%2,%3}, [%4];" \
        : "=r"((v).x), "=r"((v).y), "=r"((v).z), "=r"((v).w) : "r"(addr))
#define LDMX4T(r0, r1, r2, r3, addr)                                         \
    asm volatile("ldmatrix.sync.aligned.m8n8.x4.trans.shared.b16 {%0,%1,%2,%3}, [%4];" \
        : "=r"(r0), "=r"(r1), "=r"(r2), "=r"(r3) : "r"(addr))

// smem geometry: A rows padded to 80B, B rows padded to 272B
#define A_ROWB 80
#define B_ROWB 272
#define SA_BYTES (128 * A_ROWB)   // 10240
#define SB_BYTES (32 * B_ROWB)    // 8704

// ============================ routing ============================
__global__ void route_kernel(const void* __restrict__ tok_raw) {
    __shared__ int s_is64;
    __shared__ int s_counts[NEXP];
    int tid = threadIdx.x;
    if (tid < NEXP) s_counts[tid] = 0;
    if (tid == 0) {
        const int* w = (const int*)tok_raw;
        int allz = 1;
        for (int i = 1; i < 512; i += 2) if (w[i] != 0) { allz = 0; break; }
        s_is64 = allz;
    }
    __syncthreads();
    const int is64 = s_is64;
    int eid[T_TOKENS / 256];
#pragma unroll
    for (int it = 0; it < T_TOKENS / 256; it++) {
        int t = tid + it * 256;
        long long v = is64 ? ((const long long*)tok_raw)[t] : (long long)((const int*)tok_raw)[t];
        if (v < 0) v = 0;
        if (v > VOCAB - 1) v = VOCAB - 1;
        int ex = (int)(v / TPE);
        if (ex > NEXP - 1) ex = NEXP - 1;
        eid[it] = ex;
        atomicAdd(&s_counts[ex], 1);
    }
    __syncthreads();
    if (tid == 0) {
        int off = 0;
        for (int ex = 0; ex < NEXP; ex++) {
            d_counts[ex] = s_counts[ex];
            d_offsets[ex] = off;
            d_cursor[ex] = off;
            off += s_counts[ex];
        }
    }
    __syncthreads();
#pragma unroll
    for (int it = 0; it < T_TOKENS / 256; it++) {
        int t = tid + it * 256;
        int pos = atomicAdd(&d_cursor[eid[it]], 1);
        d_perm[pos] = t;
    }
}

// ============================================================================
// GEMM1: x[perm] (fp32->fp16) x [Wg|Wu interleaved fp16] -> h=silu(g)*u (fp16)
// block 128 rows x 128 comb cols (64 h cols). grid (16, 32, 8). BK=32.
// ============================================================================
__global__ __launch_bounds__(256, 2) void gemm1_kernel(
    const float* __restrict__ x,
    const float* __restrict__ Wg,
    const float* __restrict__ Wu)
{
    const int e = blockIdx.z;
    const int cnt = d_counts[e];
    const int row0 = blockIdx.y * 128;
    if (row0 >= cnt) return;
    const int off = d_offsets[e];
    const int bx = blockIdx.x;

    __shared__ __align__(16) char sA[SA_BYTES];
    __shared__ __align__(16) char sB[SB_BYTES];
    const uint32_t sAu = smem_u32(sA), sBu = smem_u32(sB);

    const int t = threadIdx.x, lane = t & 31, w = t >> 5;
    const int wm = w & 1, wn = w >> 1;

    // ---- A stage: thread -> row ar, 16-k slice kh ----
    const int ar = t & 127, kh = t >> 7;
    int arr = row0 + ar; if (arr >= cnt) arr = cnt - 1;
    const float* pA = x + (size_t)d_perm[off + arr] * D_HID + kh * 16;
    const uint32_t aSt = sAu + ar * A_ROWB + kh * 32;

    // ---- B stage: thread -> k row (t>>3), col-group g (t&7), 8 gate + 8 up ----
    const int bk = t >> 3, bg = t & 7;
    const float* pG = Wg + (size_t)e * D_HID * HE + (size_t)bk * HE + bx * 64 + bg * 8;
    const float* pU = Wu + (size_t)e * D_HID * HE + (size_t)bk * HE + bx * 64 + bg * 8;
    const uint32_t bSt = sBu + bk * B_ROWB + bg * 32;

    // ldmatrix per-lane offsets
    const uint32_t a_off = (((lane & 7) + ((lane >> 3) & 1) * 8) * A_ROWB) + (lane >> 4) * 16;
    const uint32_t b_off = (((lane & 7) + ((lane >> 3) & 1) * 8) * B_ROWB) + (lane >> 4) * 16;

    float acc[4][4][4] = {};
    float4 rA[4], rG[2], rU[2];

#pragma unroll
    for (int i = 0; i < 4; i++) rA[i] = *(const float4*)(pA + i * 4);
    rG[0] = *(const float4*)(pG); rG[1] = *(const float4*)(pG + 4);
    rU[0] = *(const float4*)(pU); rU[1] = *(const float4*)(pU + 4);

    for (int kc = 0; kc < D_HID / 32; kc++) {
        // STS A: 16 floats -> 8 half2 -> 2 STS.128
        {
            const float* f = (const float*)rA;
            __align__(16) __half2 hv[8];
#pragma unroll
            for (int j = 0; j < 8; j++) hv[j] = __floats2half2_rn(f[2 * j], f[2 * j + 1]);
            *(uint4*)(sA + (aSt - sAu))      = *(uint4*)&hv[0];
            *(uint4*)(sA + (aSt - sAu) + 16) = *(uint4*)&hv[4];
        }
        // STS B: interleave (gate,up) pairs -> 8 half2 -> 2 STS.128
        {
            const float* gf = (const float*)rG;
            const float* uf = (const float*)rU;
            __align__(16) __half2 hv[8];
#pragma unroll
            for (int i = 0; i < 8; i++) hv[i] = __floats2half2_rn(gf[i], uf[i]);
            *(uint4*)(sB + (bSt - sBu))      = *(uint4*)&hv[0];
            *(uint4*)(sB + (bSt - sBu) + 16) = *(uint4*)&hv[4];
        }
        __syncthreads();
        if (kc + 1 < D_HID / 32) {
            const int kn = (kc + 1) * 32;
#pragma unroll
            for (int i = 0; i < 4; i++) rA[i] = *(const float4*)(pA + kn + i * 4);
            rG[0] = *(const float4*)(pG + (size_t)kn * HE);
            rG[1] = *(const float4*)(pG + (size_t)kn * HE + 4);
            rU[0] = *(const float4*)(pU + (size_t)kn * HE);
            rU[1] = *(const float4*)(pU + (size_t)kn * HE + 4);
        }
#pragma unroll
        for (int ks = 0; ks < 2; ks++) {
            uint4 a[4]; uint2 b[4];
#pragma unroll
            for (int mi = 0; mi < 4; mi++)
                LDMX4(a[mi], sAu + (wm * 4 + mi) * (16 * A_ROWB) + ks * 32 + a_off);
#pragma unroll
            for (int j = 0; j < 2; j++) {
                uint32_t r0, r1, r2, r3;
                LDMX4T(r0, r1, r2, r3, sBu + ks * (16 * B_ROWB) + (wn * 4 + 2 * j) * 16 + b_off);
                b[2 * j].x = r0;     b[2 * j].y = r1;
                b[2 * j + 1].x = r2; b[2 * j + 1].y = r3;
            }
#pragma unroll
            for (int mi = 0; mi < 4; mi++)
#pragma unroll
                for (int ni = 0; ni < 4; ni++)
                    mma16(acc[mi][ni], a[mi], b[ni]);
        }
        __syncthreads();
    }

    // epilogue: (c0,c1)=(gate,up) of one h element; rows r, r+8
    const int q = lane & 3;
#pragma unroll
    for (int mi = 0; mi < 4; mi++) {
        int r1 = row0 + wm * 64 + mi * 16 + (lane >> 2), r2 = r1 + 8;
#pragma unroll
        for (int ni = 0; ni < 4; ni++) {
            int hc = bx * 64 + wn * 16 + ni * 4 + q;
            if (r1 < cnt) {
                float g = acc[mi][ni][0], u = acc[mi][ni][1];
                d_hbufh[(size_t)(off + r1) * HE + hc] = __float2half_rn(g / (1.f + __expf(-g)) * u);
            }
            if (r2 < cnt) {
                float g = acc[mi][ni][2], u = acc[mi][ni][3];
                d_hbufh[(size_t)(off + r2) * HE + hc] = __float2half_rn(g / (1.f + __expf(-g)) * u);
            }
        }
    }
}

// ============================================================================
// GEMM2: h (fp16) x Wd (fp32->fp16) -> out fp32, scatter via perm
// block 128 rows x 128 cols. grid (16, 32, 8). BK=32 over HE.
// ============================================================================
__global__ __launch_bounds__(256, 2) void gemm2_kernel(
    const float* __restrict__ Wd,
    float* __restrict__ out)
{
    const int e = blockIdx.z;
    const int cnt = d_counts[e];
    const int row0 = blockIdx.y * 128;
    if (row0 >= cnt) return;
    const int off = d_offsets[e];
    const int bx = blockIdx.x;

    __shared__ __align__(16) char sA[SA_BYTES];
    __shared__ __align__(16) char sB[SB_BYTES];
    const uint32_t sAu = smem_u32(sA), sBu = smem_u32(sB);

    const int t = threadIdx.x, lane = t & 31, w = t >> 5;
    const int wm = w & 1, wn = w >> 1;

    // A stage: fp16 rows, direct copy
    const int ar = t & 127, kh = t >> 7;
    int hr = off + row0 + ar; if (hr > T_TOKENS - 1) hr = T_TOKENS - 1;
    const char* pA = (const char*)(d_hbufh + (size_t)hr * HE) + kh * 32;
    const uint32_t aSt = sAu + ar * A_ROWB + kh * 32;

    // B stage: k row (t>>3), 16 cols group (t&7)
    const int bk = t >> 3, bg = t & 7;
    const float* pB = Wd + (size_t)e * HE * D_HID + (size_t)bk * D_HID + bx * 128 + bg * 16;
    const uint32_t bSt = sBu + bk * B_ROWB + bg * 32;

    const uint32_t a_off = (((lane & 7) + ((lane >> 3) & 1) * 8) * A_ROWB) + (lane >> 4) * 16;
    const uint32_t b_off = (((lane & 7) + ((lane >> 3) & 1) * 8) * B_ROWB) + (lane >> 4) * 16;

    float acc[4][4][4] = {};
    uint4 rA[2];
    float4 rB[4];

    rA[0] = *(const uint4*)(pA); rA[1] = *(const uint4*)(pA + 16);
#pragma unroll
    for (int i = 0; i < 4; i++) rB[i] = *(const float4*)(pB + i * 4);

    for (int kc = 0; kc < HE / 32; kc++) {
        *(uint4*)(sA + (aSt - sAu))      = rA[0];
        *(uint4*)(sA + (aSt - sAu) + 16) = rA[1];
        {
            const float* f = (const float*)rB;
            __align__(16) __half2 hv[8];
#pragma unroll
            for (int j = 0; j < 8; j++) hv[j] = __floats2half2_rn(f[2 * j], f[2 * j + 1]);
            *(uint4*)(sB + (bSt - sBu))      = *(uint4*)&hv[0];
            *(uint4*)(sB + (bSt - sBu) + 16) = *(uint4*)&hv[4];
        }
        __syncthreads();
        if (kc + 1 < HE / 32) {
            const int kn = (kc + 1) * 32;
            rA[0] = *(const uint4*)(pA + kn * 2);
            rA[1] = *(const uint4*)(pA + kn * 2 + 16);
#pragma unroll
            for (int i = 0; i < 4; i++)
                rB[i] = *(const float4*)(pB + (size_t)kn * D_HID + i * 4);
        }
#pragma unroll
        for (int ks = 0; ks < 2; ks++) {
            uint4 a[4]; uint2 b[4];
#pragma unroll
            for (int mi = 0; mi < 4; mi++)
                LDMX4(a[mi], sAu + (wm * 4 + mi) * (16 * A_ROWB) + ks * 32 + a_off);
#pragma unroll
            for (int j = 0; j < 2; j++) {
                uint32_t r0, r1, r2, r3;
                LDMX4T(r0, r1, r2, r3, sBu + ks * (16 * B_ROWB) + (wn * 4 + 2 * j) * 16 + b_off);
                b[2 * j].x = r0;     b[2 * j].y = r1;
                b[2 * j + 1].x = r2; b[2 * j + 1].y = r3;
            }
#pragma unroll
            for (int mi = 0; mi < 4; mi++)
#pragma unroll
                for (int ni = 0; ni < 4; ni++)
                    mma16(acc[mi][ni], a[mi], b[ni]);
        }
        __syncthreads();
    }

    const int q = lane & 3;
#pragma unroll
    for (int mi = 0; mi < 4; mi++) {
        int r1 = row0 + wm * 64 + mi * 16 + (lane >> 2), r2 = r1 + 8;
#pragma unroll
        for (int ni = 0; ni < 4; ni++) {
            int col = bx * 128 + wn * 32 + ni * 8 + 2 * q;
            if (r1 < cnt) {
                float2 v; v.x = acc[mi][ni][0]; v.y = acc[mi][ni][1];
                *(float2*)(out + (size_t)d_perm[off + r1] * D_HID + col) = v;
            }
            if (r2 < cnt) {
                float2 v; v.x = acc[mi][ni][2]; v.y = acc[mi][ni][3];
                *(float2*)(out + (size_t)d_perm[off + r2] * D_HID + col) = v;
            }
        }
    }
}

// ============================ launch ============================
extern "C" void kernel_launch(void* const* d_in, const int* in_sizes, int n_in,
                              void* d_out, int out_size) {
    const float* x   = (const float*)d_in[0];
    const void*  tok = d_in[1];
    const float* Wg  = (const float*)d_in[2];
    const float* Wu  = (const float*)d_in[3];
    const float* Wd  = (const float*)d_in[4];
    float* out = (float*)d_out;

    route_kernel<<<1, 256>>>(tok);
    gemm1_kernel<<<dim3(HE / 64,    T_TOKENS / 128, NEXP), 256>>>(x, Wg, Wu);
    gemm2_kernel<<<dim3(D_HID / 128, T_TOKENS / 128, NEXP), 256>>>(Wd, out);
}

// round 6
// speedup vs baseline: 3.6418x; 1.0044x over previous
#include <cuda_runtime.h>
#include <cuda_fp16.h>
#include <cstdint>

#define T_TOKENS 4096
#define D_HID    2048
#define HE       1024
#define NEXP     8
#define VOCAB    100000
#define TPE      12500

// ---- device scratch (no allocs allowed) ----
__device__ int    d_counts[NEXP];
__device__ int    d_offsets[NEXP];
__device__ int    d_cursor[NEXP];
__device__ int    d_perm[T_TOKENS];
__device__ __half d_hbufh[(size_t)T_TOKENS * HE];   // 8 MB, permuted rows, fp16

// ============================ PTX helpers ============================
__device__ __forceinline__ uint32_t smem_u32(const void* p) {
    uint32_t a;
    asm("{ .reg .u64 t; cvta.to.shared.u64 t, %1; cvt.u32.u64 %0, t; }" : "=r"(a) : "l"(p));
    return a;
}
// m16n8k16 fp16 mma, fp32 accum
__device__ __forceinline__ void mma16(float* c, const uint4& a, const uint2& b) {
    asm volatile(
        "mma.sync.aligned.m16n8k16.row.col.f32.f16.f16.f32 "
        "{%0,%1,%2,%3},{%4,%5,%6,%7},{%8,%9},{%0,%1,%2,%3};"
        : "+f"(c[0]), "+f"(c[1]), "+f"(c[2]), "+f"(c[3])
        : "r"(a.x), "r"(a.y), "r"(a.z), "r"(a.w), "r"(b.x), "r"(b.y));
}
#define LDMX4(v, addr)                                                       \
    asm volatile("ldmatrix.sync.aligned.m8n8.x4.shared.b16 {%0,%1,%2,%3}, [%4];" \
        : "=r"((v).x), "=r"((v).y), "=r"((v).z), "=r"((v).w) : "r"(addr))
#define LDMX4T(r0, r1, r2, r3, addr)                                         \
    asm volatile("ldmatrix.sync.aligned.m8n8.x4.trans.shared.b16 {%0,%1,%2,%3}, [%4];" \
        : "=r"(r0), "=r"(r1), "=r"(r2), "=r"(r3) : "r"(addr))

// smem geometry: A rows padded to 80B, B rows padded to 272B; double-buffered
#define A_ROWB 80
#define B_ROWB 272
#define SA_BYTES (128 * A_ROWB)   // 10240
#define SB_BYTES (32 * B_ROWB)    // 8704

// ============================ routing ============================
__global__ void route_kernel(const void* __restrict__ tok_raw) {
    __shared__ int s_is64;
    __shared__ int s_counts[NEXP];
    int tid = threadIdx.x;
    if (tid < NEXP) s_counts[tid] = 0;
    if (tid == 0) {
        const int* w = (const int*)tok_raw;
        int allz = 1;
        for (int i = 1; i < 512; i += 2) if (w[i] != 0) { allz = 0; break; }
        s_is64 = allz;
    }
    __syncthreads();
    const int is64 = s_is64;
    int eid[T_TOKENS / 256];
#pragma unroll
    for (int it = 0; it < T_TOKENS / 256; it++) {
        int t = tid + it * 256;
        long long v = is64 ? ((const long long*)tok_raw)[t] : (long long)((const int*)tok_raw)[t];
        if (v < 0) v = 0;
        if (v > VOCAB - 1) v = VOCAB - 1;
        int ex = (int)(v / TPE);
        if (ex > NEXP - 1) ex = NEXP - 1;
        eid[it] = ex;
        atomicAdd(&s_counts[ex], 1);
    }
    __syncthreads();
    if (tid == 0) {
        int off = 0;
        for (int ex = 0; ex < NEXP; ex++) {
            d_counts[ex] = s_counts[ex];
            d_offsets[ex] = off;
            d_cursor[ex] = off;
            off += s_counts[ex];
        }
    }
    __syncthreads();
#pragma unroll
    for (int it = 0; it < T_TOKENS / 256; it++) {
        int t = tid + it * 256;
        int pos = atomicAdd(&d_cursor[eid[it]], 1);
        d_perm[pos] = t;
    }
}

// ============================================================================
// GEMM1: x[perm] (fp32->fp16) x [Wg|Wu interleaved fp16] -> h=silu(g)*u (fp16)
// block 128 rows x 128 comb cols (64 h cols). grid (16, 32, 8). BK=32.
// Double-buffered: one __syncthreads per K-chunk.
// ============================================================================
__global__ __launch_bounds__(256, 2) void gemm1_kernel(
    const float* __restrict__ x,
    const float* __restrict__ Wg,
    const float* __restrict__ Wu)
{
    const int e = blockIdx.z;
    const int cnt = d_counts[e];
    const int row0 = blockIdx.y * 128;
    if (row0 >= cnt) return;
    const int off = d_offsets[e];
    const int bx = blockIdx.x;

    __shared__ __align__(16) char sA[2][SA_BYTES];
    __shared__ __align__(16) char sB[2][SB_BYTES];
    const uint32_t sAu = smem_u32(sA), sBu = smem_u32(sB);

    const int t = threadIdx.x, lane = t & 31, w = t >> 5;
    const int wm = w & 1, wn = w >> 1;

    // ---- A stage: thread -> row ar, 16-k slice kh ----
    const int ar = t & 127, kh = t >> 7;
    int arr = row0 + ar; if (arr >= cnt) arr = cnt - 1;
    const float* pA = x + (size_t)d_perm[off + arr] * D_HID + kh * 16;
    const uint32_t aStOff = ar * A_ROWB + kh * 32;

    // ---- B stage: thread -> k row (t>>3), col-group g (t&7), 8 gate + 8 up ----
    const int bk = t >> 3, bg = t & 7;
    const float* pG = Wg + (size_t)e * D_HID * HE + (size_t)bk * HE + bx * 64 + bg * 8;
    const float* pU = Wu + (size_t)e * D_HID * HE + (size_t)bk * HE + bx * 64 + bg * 8;
    const uint32_t bStOff = bk * B_ROWB + bg * 32;

    // ldmatrix per-lane offsets
    const uint32_t a_off = (((lane & 7) + ((lane >> 3) & 1) * 8) * A_ROWB) + (lane >> 4) * 16;
    const uint32_t b_off = (((lane & 7) + ((lane >> 3) & 1) * 8) * B_ROWB) + (lane >> 4) * 16;

    float acc[4][4][4] = {};
    float4 rA[4], rG[2], rU[2];

    // prologue: load + stage chunk 0 into buffer 0
#pragma unroll
    for (int i = 0; i < 4; i++) rA[i] = *(const float4*)(pA + i * 4);
    rG[0] = *(const float4*)(pG); rG[1] = *(const float4*)(pG + 4);
    rU[0] = *(const float4*)(pU); rU[1] = *(const float4*)(pU + 4);
    {
        const float* f = (const float*)rA;
        __align__(16) __half2 hv[8];
#pragma unroll
        for (int j = 0; j < 8; j++) hv[j] = __floats2half2_rn(f[2 * j], f[2 * j + 1]);
        *(uint4*)(sA[0] + aStOff)      = *(uint4*)&hv[0];
        *(uint4*)(sA[0] + aStOff + 16) = *(uint4*)&hv[4];
        const float* gf = (const float*)rG;
        const float* uf = (const float*)rU;
        __align__(16) __half2 bv[8];
#pragma unroll
        for (int i = 0; i < 8; i++) bv[i] = __floats2half2_rn(gf[i], uf[i]);
        *(uint4*)(sB[0] + bStOff)      = *(uint4*)&bv[0];
        *(uint4*)(sB[0] + bStOff + 16) = *(uint4*)&bv[4];
    }
    __syncthreads();

    for (int kc = 0; kc < D_HID / 32; kc++) {
        const int cur = kc & 1;
        const bool more = (kc + 1 < D_HID / 32);
        if (more) {
            const int kn = (kc + 1) * 32;
#pragma unroll
            for (int i = 0; i < 4; i++) rA[i] = *(const float4*)(pA + kn + i * 4);
            rG[0] = *(const float4*)(pG + (size_t)kn * HE);
            rG[1] = *(const float4*)(pG + (size_t)kn * HE + 4);
            rU[0] = *(const float4*)(pU + (size_t)kn * HE);
            rU[1] = *(const float4*)(pU + (size_t)kn * HE + 4);
        }
        // compute on buffer cur
        const uint32_t sAc = sAu + cur * SA_BYTES;
        const uint32_t sBc = sBu + cur * SB_BYTES;
#pragma unroll
        for (int ks = 0; ks < 2; ks++) {
            uint4 a[4]; uint2 b[4];
#pragma unroll
            for (int mi = 0; mi < 4; mi++)
                LDMX4(a[mi], sAc + (wm * 4 + mi) * (16 * A_ROWB) + ks * 32 + a_off);
#pragma unroll
            for (int j = 0; j < 2; j++) {
                uint32_t r0, r1, r2, r3;
                LDMX4T(r0, r1, r2, r3, sBc + ks * (16 * B_ROWB) + (wn * 4 + 2 * j) * 16 + b_off);
                b[2 * j].x = r0;     b[2 * j].y = r1;
                b[2 * j + 1].x = r2; b[2 * j + 1].y = r3;
            }
#pragma unroll
            for (int mi = 0; mi < 4; mi++)
#pragma unroll
                for (int ni = 0; ni < 4; ni++)
                    mma16(acc[mi][ni], a[mi], b[ni]);
        }
        // stage chunk kc+1 into the other buffer
        if (more) {
            char* dA = sA[1 - cur];
            char* dB = sB[1 - cur];
            const float* f = (const float*)rA;
            __align__(16) __half2 hv[8];
#pragma unroll
            for (int j = 0; j < 8; j++) hv[j] = __floats2half2_rn(f[2 * j], f[2 * j + 1]);
            *(uint4*)(dA + aStOff)      = *(uint4*)&hv[0];
            *(uint4*)(dA + aStOff + 16) = *(uint4*)&hv[4];
            const float* gf = (const float*)rG;
            const float* uf = (const float*)rU;
            __align__(16) __half2 bv[8];
#pragma unroll
            for (int i = 0; i < 8; i++) bv[i] = __floats2half2_rn(gf[i], uf[i]);
            *(uint4*)(dB + bStOff)      = *(uint4*)&bv[0];
            *(uint4*)(dB + bStOff + 16) = *(uint4*)&bv[4];
        }
        __syncthreads();
    }

    // epilogue: (c0,c1)=(gate,up) of one h element; rows r, r+8
    const int q = lane & 3;
#pragma unroll
    for (int mi = 0; mi < 4; mi++) {
        int r1 = row0 + wm * 64 + mi * 16 + (lane >> 2), r2 = r1 + 8;
#pragma unroll
        for (int ni = 0; ni < 4; ni++) {
            int hc = bx * 64 + wn * 16 + ni * 4 + q;
            if (r1 < cnt) {
                float g = acc[mi][ni][0], u = acc[mi][ni][1];
                d_hbufh[(size_t)(off + r1) * HE + hc] = __float2half_rn(g / (1.f + __expf(-g)) * u);
            }
            if (r2 < cnt) {
                float g = acc[mi][ni][2], u = acc[mi][ni][3];
                d_hbufh[(size_t)(off + r2) * HE + hc] = __float2half_rn(g / (1.f + __expf(-g)) * u);
            }
        }
    }
}

// ============================================================================
// GEMM2: h (fp16) x Wd (fp32->fp16) -> out fp32, scatter via perm
// block 128 rows x 128 cols. grid (16, 32, 8). BK=32 over HE. Double-buffered.
// ============================================================================
__global__ __launch_bounds__(256, 2) void gemm2_kernel(
    const float* __restrict__ Wd,
    float* __restrict__ out)
{
    const int e = blockIdx.z;
    const int cnt = d_counts[e];
    const int row0 = blockIdx.y * 128;
    if (row0 >= cnt) return;
    const int off = d_offsets[e];
    const int bx = blockIdx.x;

    __shared__ __align__(16) char sA[2][SA_BYTES];
    __shared__ __align__(16) char sB[2][SB_BYTES];
    const uint32_t sAu = smem_u32(sA), sBu = smem_u32(sB);

    const int t = threadIdx.x, lane = t & 31, w = t >> 5;
    const int wm = w & 1, wn = w >> 1;

    // A stage: fp16 rows, direct copy
    const int ar = t & 127, kh = t >> 7;
    int hr = off + row0 + ar; if (hr > T_TOKENS - 1) hr = T_TOKENS - 1;
    const char* pA = (const char*)(d_hbufh + (size_t)hr * HE) + kh * 32;
    const uint32_t aStOff = ar * A_ROWB + kh * 32;

    // B stage: k row (t>>3), 16 cols group (t&7)
    const int bk = t >> 3, bg = t & 7;
    const float* pB = Wd + (size_t)e * HE * D_HID + (size_t)bk * D_HID + bx * 128 + bg * 16;
    const uint32_t bStOff = bk * B_ROWB + bg * 32;

    const uint32_t a_off = (((lane & 7) + ((lane >> 3) & 1) * 8) * A_ROWB) + (lane >> 4) * 16;
    const uint32_t b_off = (((lane & 7) + ((lane >> 3) & 1) * 8) * B_ROWB) + (lane >> 4) * 16;

    float acc[4][4][4] = {};
    uint4 rA[2];
    float4 rB[4];

    rA[0] = *(const uint4*)(pA); rA[1] = *(const uint4*)(pA + 16);
#pragma unroll
    for (int i = 0; i < 4; i++) rB[i] = *(const float4*)(pB + i * 4);
    {
        *(uint4*)(sA[0] + aStOff)      = rA[0];
        *(uint4*)(sA[0] + aStOff + 16) = rA[1];
        const float* f = (const float*)rB;
        __align__(16) __half2 hv[8];
#pragma unroll
        for (int j = 0; j < 8; j++) hv[j] = __floats2half2_rn(f[2 * j], f[2 * j + 1]);
        *(uint4*)(sB[0] + bStOff)      = *(uint4*)&hv[0];
        *(uint4*)(sB[0] + bStOff + 16) = *(uint4*)&hv[4];
    }
    __syncthreads();

    for (int kc = 0; kc < HE / 32; kc++) {
        const int cur = kc & 1;
        const bool more = (kc + 1 < HE / 32);
        if (more) {
            const int kn = (kc + 1) * 32;
            rA[0] = *(const uint4*)(pA + kn * 2);
            rA[1] = *(const uint4*)(pA + kn * 2 + 16);
#pragma unroll
            for (int i = 0; i < 4; i++)
                rB[i] = *(const float4*)(pB + (size_t)kn * D_HID + i * 4);
        }
        const uint32_t sAc = sAu + cur * SA_BYTES;
        const uint32_t sBc = sBu + cur * SB_BYTES;
#pragma unroll
        for (int ks = 0; ks < 2; ks++) {
            uint4 a[4]; uint2 b[4];
#pragma unroll
            for (int mi = 0; mi < 4; mi++)
                LDMX4(a[mi], sAc + (wm * 4 + mi) * (16 * A_ROWB) + ks * 32 + a_off);
#pragma unroll
            for (int j = 0; j < 2; j++) {
                uint32_t r0, r1, r2, r3;
                LDMX4T(r0, r1, r2, r3, sBc + ks * (16 * B_ROWB) + (wn * 4 + 2 * j) * 16 + b_off);
                b[2 * j].x = r0;     b[2 * j].y = r1;
                b[2 * j + 1].x = r2; b[2 * j + 1].y = r3;
            }
#pragma unroll
            for (int mi = 0; mi < 4; mi++)
#pragma unroll
                for (int ni = 0; ni < 4; ni++)
                    mma16(acc[mi][ni], a[mi], b[ni]);
        }
        if (more) {
            char* dA = sA[1 - cur];
            char* dB = sB[1 - cur];
            *(uint4*)(dA + aStOff)      = rA[0];
            *(uint4*)(dA + aStOff + 16) = rA[1];
            const float* f = (const float*)rB;
            __align__(16) __half2 hv[8];
#pragma unroll
            for (int j = 0; j < 8; j++) hv[j] = __floats2half2_rn(f[2 * j], f[2 * j + 1]);
            *(uint4*)(dB + bStOff)      = *(uint4*)&hv[0];
            *(uint4*)(dB + bStOff + 16) = *(uint4*)&hv[4];
        }
        __syncthreads();
    }

    const int q = lane & 3;
#pragma unroll
    for (int mi = 0; mi < 4; mi++) {
        int r1 = row0 + wm * 64 + mi * 16 + (lane >> 2), r2 = r1 + 8;
#pragma unroll
        for (int ni = 0; ni < 4; ni++) {
            int col = bx * 128 + wn * 32 + ni * 8 + 2 * q;
            if (r1 < cnt) {
                float2 v; v.x = acc[mi][ni][0]; v.y = acc[mi][ni][1];
                *(float2*)(out + (size_t)d_perm[off + r1] * D_HID + col) = v;
            }
            if (r2 < cnt) {
                float2 v; v.x = acc[mi][ni][2]; v.y = acc[mi][ni][3];
                *(float2*)(out + (size_t)d_perm[off + r2] * D_HID + col) = v;
            }
        }
    }
}

// ============================ launch ============================
extern "C" void kernel_launch(void* const* d_in, const int* in_sizes, int n_in,
                              void* d_out, int out_size) {
    const float* x   = (const float*)d_in[0];
    const void*  tok = d_in[1];
    const float* Wg  = (const float*)d_in[2];
    const float* Wu  = (const float*)d_in[3];
    const float* Wd  = (const float*)d_in[4];
    float* out = (float*)d_out;

    route_kernel<<<1, 256>>>(tok);
    gemm1_kernel<<<dim3(HE / 64,    T_TOKENS / 128, NEXP), 256>>>(x, Wg, Wu);
    gemm2_kernel<<<dim3(D_HID / 128, T_TOKENS / 128, NEXP), 256>>>(Wd, out);
}

// round 7
// speedup vs baseline: 4.8938x; 1.3438x over previous
#include <cuda_runtime.h>
#include <cuda_fp16.h>
#include <cstdint>

#define T_TOKENS 4096
#define D_HID    2048
#define HE       1024
#define NEXP     8
#define VOCAB    100000
#define TPE      12500

// ---- device scratch (no allocs allowed) ----
__device__ int    d_counts[NEXP];
__device__ int    d_offsets[NEXP];
__device__ int    d_cursor[NEXP];
__device__ int    d_perm[T_TOKENS];
__device__ __half d_hbufh[(size_t)T_TOKENS * HE];              // 8 MB
__device__ __half d_xh[(size_t)T_TOKENS * D_HID];              // 16 MB
__device__ __half d_wguh[(size_t)NEXP * D_HID * 2 * HE];       // 64 MB [e][k][2048] gate/up interleaved
__device__ __half d_wdh[(size_t)NEXP * HE * D_HID];            // 32 MB [e][k][2048]

// ============================ PTX helpers ============================
__device__ __forceinline__ uint32_t smem_u32(const void* p) {
    uint32_t a;
    asm("{ .reg .u64 t; cvta.to.shared.u64 t, %1; cvt.u32.u64 %0, t; }" : "=r"(a) : "l"(p));
    return a;
}
__device__ __forceinline__ void mma16(float* c, const uint4& a, const uint2& b) {
    asm volatile(
        "mma.sync.aligned.m16n8k16.row.col.f32.f16.f16.f32 "
        "{%0,%1,%2,%3},{%4,%5,%6,%7},{%8,%9},{%0,%1,%2,%3};"
        : "+f"(c[0]), "+f"(c[1]), "+f"(c[2]), "+f"(c[3])
        : "r"(a.x), "r"(a.y), "r"(a.z), "r"(a.w), "r"(b.x), "r"(b.y));
}
#define LDMX4(v, addr)                                                       \
    asm volatile("ldmatrix.sync.aligned.m8n8.x4.shared.b16 {%0,%1,%2,%3}, [%4];" \
        : "=r"((v).x), "=r"((v).y), "=r"((v).z), "=r"((v).w) : "r"(addr))
#define LDMX4T(r0, r1, r2, r3, addr)                                         \
    asm volatile("ldmatrix.sync.aligned.m8n8.x4.trans.shared.b16 {%0,%1,%2,%3}, [%4];" \
        : "=r"(r0), "=r"(r1), "=r"(r2), "=r"(r3) : "r"(addr))
#define CPA16(dst, src) \
    asm volatile("cp.async.cg.shared.global [%0], [%1], 16;" :: "r"(dst), "l"(src) : "memory")
#define CP_COMMIT() asm volatile("cp.async.commit_group;" ::: "memory")
#define CP_WAIT(n)  asm volatile("cp.async.wait_group %0;" :: "n"(n) : "memory")

// smem geometry: A rows 80B (64B data + 16 pad), B rows 272B (256B data + 16 pad)
#define A_ROWB 80
#define B_ROWB 272
#define SLOT_A (128 * A_ROWB)      // 10240
#define SLOT_B (32 * B_ROWB)       // 8704
#define NSTAGE 4
#define SMEM_TOT (NSTAGE * (SLOT_A + SLOT_B))   // 75776

// ============================ routing ============================
__global__ void route_kernel(const void* __restrict__ tok_raw) {
    __shared__ int s_is64;
    __shared__ int s_counts[NEXP];
    int tid = threadIdx.x;
    if (tid < NEXP) s_counts[tid] = 0;
    if (tid == 0) {
        const int* w = (const int*)tok_raw;
        int allz = 1;
        for (int i = 1; i < 512; i += 2) if (w[i] != 0) { allz = 0; break; }
        s_is64 = allz;
    }
    __syncthreads();
    const int is64 = s_is64;
    int eid[T_TOKENS / 256];
#pragma unroll
    for (int it = 0; it < T_TOKENS / 256; it++) {
        int t = tid + it * 256;
        long long v = is64 ? ((const long long*)tok_raw)[t] : (long long)((const int*)tok_raw)[t];
        if (v < 0) v = 0;
        if (v > VOCAB - 1) v = VOCAB - 1;
        int ex = (int)(v / TPE);
        if (ex > NEXP - 1) ex = NEXP - 1;
        eid[it] = ex;
        atomicAdd(&s_counts[ex], 1);
    }
    __syncthreads();
    if (tid == 0) {
        int off = 0;
        for (int ex = 0; ex < NEXP; ex++) {
            d_counts[ex] = s_counts[ex];
            d_offsets[ex] = off;
            d_cursor[ex] = off;
            off += s_counts[ex];
        }
    }
    __syncthreads();
#pragma unroll
    for (int it = 0; it < T_TOKENS / 256; it++) {
        int t = tid + it * 256;
        int pos = atomicAdd(&d_cursor[eid[it]], 1);
        d_perm[pos] = t;
    }
}

// ============================ converters ============================
__global__ __launch_bounds__(256) void conv_x_kernel(const float* __restrict__ x) {
    size_t gid = (size_t)blockIdx.x * 256 + threadIdx.x;   // one 16B output per thread
    const float4* s = (const float4*)x + gid * 2;
    float4 a = s[0], b = s[1];
    __align__(16) __half2 h[4];
    h[0] = __floats2half2_rn(a.x, a.y); h[1] = __floats2half2_rn(a.z, a.w);
    h[2] = __floats2half2_rn(b.x, b.y); h[3] = __floats2half2_rn(b.z, b.w);
    *((uint4*)d_xh + gid) = *(uint4*)h;
}
// gate/up interleave: out[e][k][2n]=g, [2n+1]=u
__global__ __launch_bounds__(256) void conv_wgu_kernel(
    const float* __restrict__ Wg, const float* __restrict__ Wu) {
    size_t gid = (size_t)blockIdx.x * 256 + threadIdx.x;   // one 16B (8 halfs = 4 (g,u) pairs)
    size_t rowAll = gid >> 8;                              // e*2048 + k
    int n0 = (int)(gid & 255) * 4;
    const float4 g = *(const float4*)(Wg + rowAll * HE + n0);
    const float4 u = *(const float4*)(Wu + rowAll * HE + n0);
    __align__(16) __half2 h[4];
    h[0] = __floats2half2_rn(g.x, u.x); h[1] = __floats2half2_rn(g.y, u.y);
    h[2] = __floats2half2_rn(g.z, u.z); h[3] = __floats2half2_rn(g.w, u.w);
    *((uint4*)d_wguh + gid) = *(uint4*)h;
}
__global__ __launch_bounds__(256) void conv_wd_kernel(const float* __restrict__ Wd) {
    size_t gid = (size_t)blockIdx.x * 256 + threadIdx.x;
    const float4* s = (const float4*)Wd + gid * 2;
    float4 a = s[0], b = s[1];
    __align__(16) __half2 h[4];
    h[0] = __floats2half2_rn(a.x, a.y); h[1] = __floats2half2_rn(a.z, a.w);
    h[2] = __floats2half2_rn(b.x, b.y); h[3] = __floats2half2_rn(b.z, b.w);
    *((uint4*)d_wdh + gid) = *(uint4*)h;
}

// ============================================================================
// GEMM1: xh[perm] x wgu (interleaved) -> h = silu(g)*u (fp16)
// block 128 rows x 128 comb cols. grid (16, 32, 8). 64 chunks of k=32.
// cp.async 4-stage pipeline, 1 barrier per chunk.
// ============================================================================
__global__ __launch_bounds__(256, 2) void gemm1_kernel() {
    const int e = blockIdx.z;
    const int cnt = d_counts[e];
    const int row0 = blockIdx.y * 128;
    if (row0 >= cnt) return;
    const int off = d_offsets[e];
    const int bx = blockIdx.x;

    extern __shared__ __align__(16) char smem[];
    const uint32_t sb = smem_u32(smem);

    const int t = threadIdx.x, lane = t & 31, w = t >> 5;
    const int wm = w & 1, wn = w >> 1;

    // ---- cp.async mappings ----
    // A: 128 rows x 64B; thread -> row t>>1, 32B seg (t&1)
    const int ar2 = t >> 1, ah = t & 1;
    int arr = row0 + ar2; if (arr >= cnt) arr = cnt - 1;
    const char* srcA = (const char*)(d_xh + (size_t)d_perm[off + arr] * D_HID) + ah * 32;
    const uint32_t dstA = sb + ar2 * A_ROWB + ah * 32;
    // B: 32 rows x 256B; thread -> row t>>3, 32B seg (t&7)
    const int bk = t >> 3, bs = t & 7;
    const char* srcB = (const char*)(d_wguh + ((size_t)e * D_HID + bk) * (2 * HE) + bx * 128 + bs * 16)
                       ;  // note: bs*16 halfs = bs*32 bytes
    const uint32_t dstB = sb + NSTAGE * SLOT_A + bk * B_ROWB + bs * 32;

    // ldmatrix per-lane offsets
    const uint32_t a_off = (((lane & 7) + ((lane >> 3) & 1) * 8) * A_ROWB) + (lane >> 4) * 16;
    const uint32_t b_off = (((lane & 7) + ((lane >> 3) & 1) * 8) * B_ROWB) + (lane >> 4) * 16;

    float acc[4][4][4] = {};

    const int NC = D_HID / 32;
    // prologue: stages 0..NSTAGE-2
#pragma unroll
    for (int s = 0; s < NSTAGE - 1; s++) {
        CPA16(dstA + s * SLOT_A, srcA + s * 64);
        CPA16(dstA + s * SLOT_A + 16, srcA + s * 64 + 16);
        CPA16(dstB + s * SLOT_B, srcB + (size_t)s * 32 * (2 * HE) * 2);
        CPA16(dstB + s * SLOT_B + 16, srcB + (size_t)s * 32 * (2 * HE) * 2 + 16);
        CP_COMMIT();
    }

    for (int kc = 0; kc < NC; kc++) {
        CP_WAIT(NSTAGE - 2);
        __syncthreads();
        const int kn = kc + NSTAGE - 1;
        if (kn < NC) {
            const int sl = kn & (NSTAGE - 1);
            CPA16(dstA + sl * SLOT_A, srcA + kn * 64);
            CPA16(dstA + sl * SLOT_A + 16, srcA + kn * 64 + 16);
            CPA16(dstB + sl * SLOT_B, srcB + (size_t)kn * 32 * (2 * HE) * 2);
            CPA16(dstB + sl * SLOT_B + 16, srcB + (size_t)kn * 32 * (2 * HE) * 2 + 16);
        }
        CP_COMMIT();
        const int cur = kc & (NSTAGE - 1);
        const uint32_t sAc = sb + cur * SLOT_A;
        const uint32_t sBc = sb + NSTAGE * SLOT_A + cur * SLOT_B;
#pragma unroll
        for (int ks = 0; ks < 2; ks++) {
            uint4 a[4]; uint2 b[4];
#pragma unroll
            for (int mi = 0; mi < 4; mi++)
                LDMX4(a[mi], sAc + (wm * 4 + mi) * (16 * A_ROWB) + ks * 32 + a_off);
#pragma unroll
            for (int j = 0; j < 2; j++) {
                uint32_t r0, r1, r2, r3;
                LDMX4T(r0, r1, r2, r3, sBc + ks * (16 * B_ROWB) + (wn * 4 + 2 * j) * 16 + b_off);
                b[2 * j].x = r0;     b[2 * j].y = r1;
                b[2 * j + 1].x = r2; b[2 * j + 1].y = r3;
            }
#pragma unroll
            for (int mi = 0; mi < 4; mi++)
#pragma unroll
                for (int ni = 0; ni < 4; ni++)
                    mma16(acc[mi][ni], a[mi], b[ni]);
        }
    }
    CP_WAIT(0);

    // epilogue: (c0,c1)=(gate,up) of one h element; rows r, r+8
    const int q = lane & 3;
#pragma unroll
    for (int mi = 0; mi < 4; mi++) {
        int r1 = row0 + wm * 64 + mi * 16 + (lane >> 2), r2 = r1 + 8;
#pragma unroll
        for (int ni = 0; ni < 4; ni++) {
            int hc = bx * 64 + wn * 16 + ni * 4 + q;
            if (r1 < cnt) {
                float g = acc[mi][ni][0], u = acc[mi][ni][1];
                d_hbufh[(size_t)(off + r1) * HE + hc] = __float2half_rn(g / (1.f + __expf(-g)) * u);
            }
            if (r2 < cnt) {
                float g = acc[mi][ni][2], u = acc[mi][ni][3];
                d_hbufh[(size_t)(off + r2) * HE + hc] = __float2half_rn(g / (1.f + __expf(-g)) * u);
            }
        }
    }
}

// ============================================================================
// GEMM2: h (fp16) x wdh -> out fp32, scatter via perm
// block 128 rows x 128 cols. grid (16, 32, 8). 32 chunks of k=32.
// ============================================================================
__global__ __launch_bounds__(256, 2) void gemm2_kernel(float* __restrict__ out) {
    const int e = blockIdx.z;
    const int cnt = d_counts[e];
    const int row0 = blockIdx.y * 128;
    if (row0 >= cnt) return;
    const int off = d_offsets[e];
    const int bx = blockIdx.x;

    extern __shared__ __align__(16) char smem[];
    const uint32_t sb = smem_u32(smem);

    const int t = threadIdx.x, lane = t & 31, w = t >> 5;
    const int wm = w & 1, wn = w >> 1;

    const int ar2 = t >> 1, ah = t & 1;
    int hr = off + row0 + ar2; if (hr > T_TOKENS - 1) hr = T_TOKENS - 1;
    const char* srcA = (const char*)(d_hbufh + (size_t)hr * HE) + ah * 32;
    const uint32_t dstA = sb + ar2 * A_ROWB + ah * 32;

    const int bk = t >> 3, bs = t & 7;
    const char* srcB = (const char*)(d_wdh + ((size_t)e * HE + bk) * D_HID + bx * 128 + bs * 16);
    const uint32_t dstB = sb + NSTAGE * SLOT_A + bk * B_ROWB + bs * 32;

    const uint32_t a_off = (((lane & 7) + ((lane >> 3) & 1) * 8) * A_ROWB) + (lane >> 4) * 16;
    const uint32_t b_off = (((lane & 7) + ((lane >> 3) & 1) * 8) * B_ROWB) + (lane >> 4) * 16;

    float acc[4][4][4] = {};

    const int NC = HE / 32;
#pragma unroll
    for (int s = 0; s < NSTAGE - 1; s++) {
        CPA16(dstA + s * SLOT_A, srcA + s * 64);
        CPA16(dstA + s * SLOT_A + 16, srcA + s * 64 + 16);
        CPA16(dstB + s * SLOT_B, srcB + (size_t)s * 32 * D_HID * 2);
        CPA16(dstB + s * SLOT_B + 16, srcB + (size_t)s * 32 * D_HID * 2 + 16);
        CP_COMMIT();
    }

    for (int kc = 0; kc < NC; kc++) {
        CP_WAIT(NSTAGE - 2);
        __syncthreads();
        const int kn = kc + NSTAGE - 1;
        if (kn < NC) {
            const int sl = kn & (NSTAGE - 1);
            CPA16(dstA + sl * SLOT_A, srcA + kn * 64);
            CPA16(dstA + sl * SLOT_A + 16, srcA + kn * 64 + 16);
            CPA16(dstB + sl * SLOT_B, srcB + (size_t)kn * 32 * D_HID * 2);
            CPA16(dstB + sl * SLOT_B + 16, srcB + (size_t)kn * 32 * D_HID * 2 + 16);
        }
        CP_COMMIT();
        const int cur = kc & (NSTAGE - 1);
        const uint32_t sAc = sb + cur * SLOT_A;
        const uint32_t sBc = sb + NSTAGE * SLOT_A + cur * SLOT_B;
#pragma unroll
        for (int ks = 0; ks < 2; ks++) {
            uint4 a[4]; uint2 b[4];
#pragma unroll
            for (int mi = 0; mi < 4; mi++)
                LDMX4(a[mi], sAc + (wm * 4 + mi) * (16 * A_ROWB) + ks * 32 + a_off);
#pragma unroll
            for (int j = 0; j < 2; j++) {
                uint32_t r0, r1, r2, r3;
                LDMX4T(r0, r1, r2, r3, sBc + ks * (16 * B_ROWB) + (wn * 4 + 2 * j) * 16 + b_off);
                b[2 * j].x = r0;     b[2 * j].y = r1;
                b[2 * j + 1].x = r2; b[2 * j + 1].y = r3;
            }
#pragma unroll
            for (int mi = 0; mi < 4; mi++)
#pragma unroll
                for (int ni = 0; ni < 4; ni++)
                    mma16(acc[mi][ni], a[mi], b[ni]);
        }
    }
    CP_WAIT(0);

    const int q = lane & 3;
#pragma unroll
    for (int mi = 0; mi < 4; mi++) {
        int r1 = row0 + wm * 64 + mi * 16 + (lane >> 2), r2 = r1 + 8;
#pragma unroll
        for (int ni = 0; ni < 4; ni++) {
            int col = bx * 128 + wn * 32 + ni * 8 + 2 * q;
            if (r1 < cnt) {
                float2 v; v.x = acc[mi][ni][0]; v.y = acc[mi][ni][1];
                *(float2*)(out + (size_t)d_perm[off + r1] * D_HID + col) = v;
            }
            if (r2 < cnt) {
                float2 v; v.x = acc[mi][ni][2]; v.y = acc[mi][ni][3];
                *(float2*)(out + (size_t)d_perm[off + r2] * D_HID + col) = v;
            }
        }
    }
}

// ============================ launch ============================
extern "C" void kernel_launch(void* const* d_in, const int* in_sizes, int n_in,
                              void* d_out, int out_size) {
    const float* x   = (const float*)d_in[0];
    const void*  tok = d_in[1];
    const float* Wg  = (const float*)d_in[2];
    const float* Wu  = (const float*)d_in[3];
    const float* Wd  = (const float*)d_in[4];
    float* out = (float*)d_out;

    cudaFuncSetAttribute(gemm1_kernel, cudaFuncAttributeMaxDynamicSharedMemorySize, SMEM_TOT);
    cudaFuncSetAttribute(gemm2_kernel, cudaFuncAttributeMaxDynamicSharedMemorySize, SMEM_TOT);

    route_kernel<<<1, 256>>>(tok);
    conv_x_kernel<<<(T_TOKENS * D_HID / 8) / 256, 256>>>(x);
    conv_wgu_kernel<<<(NEXP * D_HID * 2 * HE / 8) / 256, 256>>>(Wg, Wu);
    conv_wd_kernel<<<(NEXP * HE * D_HID / 8) / 256, 256>>>(Wd);

    gemm1_kernel<<<dim3(HE / 64,    T_TOKENS / 128, NEXP), 256, SMEM_TOT>>>();
    gemm2_kernel<<<dim3(D_HID / 128, T_TOKENS / 128, NEXP), 256, SMEM_TOT>>>(out);
}

// round 8
// speedup vs baseline: 5.0774x; 1.0375x over previous
#include <cuda_runtime.h>
#include <cuda_fp16.h>
#include <cstdint>

#define T_TOKENS 4096
#define D_HID    2048
#define HE       1024
#define NEXP     8
#define VOCAB    100000
#define TPE      12500

// ---- device scratch (no allocs allowed) ----
__device__ int    d_counts[NEXP];
__device__ int    d_offsets[NEXP];
__device__ int    d_cursor[NEXP];
__device__ int    d_perm[T_TOKENS];
__device__ __half d_hbufh[(size_t)T_TOKENS * HE];              // 8 MB
__device__ __half d_xh[(size_t)T_TOKENS * D_HID];              // 16 MB
__device__ __half d_wguh[(size_t)NEXP * D_HID * 2 * HE];       // 64 MB [e][k][2048] gate/up interleaved
__device__ __half d_wdh[(size_t)NEXP * HE * D_HID];            // 32 MB [e][k][2048]

// ============================ PTX helpers ============================
__device__ __forceinline__ uint32_t smem_u32(const void* p) {
    uint32_t a;
    asm("{ .reg .u64 t; cvta.to.shared.u64 t, %1; cvt.u32.u64 %0, t; }" : "=r"(a) : "l"(p));
    return a;
}
__device__ __forceinline__ void mma16(float* c, const uint4& a, const uint2& b) {
    asm volatile(
        "mma.sync.aligned.m16n8k16.row.col.f32.f16.f16.f32 "
        "{%0,%1,%2,%3},{%4,%5,%6,%7},{%8,%9},{%0,%1,%2,%3};"
        : "+f"(c[0]), "+f"(c[1]), "+f"(c[2]), "+f"(c[3])
        : "r"(a.x), "r"(a.y), "r"(a.z), "r"(a.w), "r"(b.x), "r"(b.y));
}
#define LDMX4(v, addr)                                                       \
    asm volatile("ldmatrix.sync.aligned.m8n8.x4.shared.b16 {%0,%1,%2,%3}, [%4];" \
        : "=r"((v).x), "=r"((v).y), "=r"((v).z), "=r"((v).w) : "r"(addr))
#define LDMX4T(r0, r1, r2, r3, addr)                                         \
    asm volatile("ldmatrix.sync.aligned.m8n8.x4.trans.shared.b16 {%0,%1,%2,%3}, [%4];" \
        : "=r"(r0), "=r"(r1), "=r"(r2), "=r"(r3) : "r"(addr))
#define CPA16(dst, src) \
    asm volatile("cp.async.cg.shared.global [%0], [%1], 16;" :: "r"(dst), "l"(src) : "memory")
#define CP_COMMIT() asm volatile("cp.async.commit_group;" ::: "memory")
#define CP_WAIT(n)  asm volatile("cp.async.wait_group %0;" :: "n"(n) : "memory")

// smem geometry: A rows 80B (64B data + 16 pad), B rows 272B (256B data + 16 pad)
#define A_ROWB 80
#define B_ROWB 272
#define SLOT_A (128 * A_ROWB)      // 10240
#define SLOT_B (32 * B_ROWB)       // 8704
#define NSTAGE 4
#define SMEM_TOT (NSTAGE * (SLOT_A + SLOT_B))   // 75776

// ============================ routing ============================
__global__ void route_kernel(const void* __restrict__ tok_raw) {
    __shared__ int s_is64;
    __shared__ int s_counts[NEXP];
    int tid = threadIdx.x;
    if (tid < NEXP) s_counts[tid] = 0;
    if (tid == 0) {
        const int* w = (const int*)tok_raw;
        int allz = 1;
        for (int i = 1; i < 512; i += 2) if (w[i] != 0) { allz = 0; break; }
        s_is64 = allz;
    }
    __syncthreads();
    const int is64 = s_is64;
    int eid[T_TOKENS / 256];
#pragma unroll
    for (int it = 0; it < T_TOKENS / 256; it++) {
        int t = tid + it * 256;
        long long v = is64 ? ((const long long*)tok_raw)[t] : (long long)((const int*)tok_raw)[t];
        if (v < 0) v = 0;
        if (v > VOCAB - 1) v = VOCAB - 1;
        int ex = (int)(v / TPE);
        if (ex > NEXP - 1) ex = NEXP - 1;
        eid[it] = ex;
        atomicAdd(&s_counts[ex], 1);
    }
    __syncthreads();
    if (tid == 0) {
        int off = 0;
        for (int ex = 0; ex < NEXP; ex++) {
            d_counts[ex] = s_counts[ex];
            d_offsets[ex] = off;
            d_cursor[ex] = off;
            off += s_counts[ex];
        }
    }
    __syncthreads();
#pragma unroll
    for (int it = 0; it < T_TOKENS / 256; it++) {
        int t = tid + it * 256;
        int pos = atomicAdd(&d_cursor[eid[it]], 1);
        d_perm[pos] = t;
    }
}

// ============================ converters (32B out per thread) ============================
__device__ __forceinline__ uint4 pack8(float4 a, float4 b) {
    __align__(16) __half2 h[4];
    h[0] = __floats2half2_rn(a.x, a.y); h[1] = __floats2half2_rn(a.z, a.w);
    h[2] = __floats2half2_rn(b.x, b.y); h[3] = __floats2half2_rn(b.z, b.w);
    return *(uint4*)h;
}
__global__ __launch_bounds__(256) void conv_x_kernel(const float* __restrict__ x) {
    size_t gid = (size_t)blockIdx.x * 256 + threadIdx.x;   // 32B (16 halfs) per thread
    const float4* s = (const float4*)x + gid * 4;
    uint4* d = (uint4*)d_xh + gid * 2;
    d[0] = pack8(s[0], s[1]);
    d[1] = pack8(s[2], s[3]);
}
// gate/up interleave: out[e][k][2n]=g, [2n+1]=u ; 16 output halfs (8 pairs) per thread
__global__ __launch_bounds__(256) void conv_wgu_kernel(
    const float* __restrict__ Wg, const float* __restrict__ Wu) {
    size_t gid = (size_t)blockIdx.x * 256 + threadIdx.x;
    size_t rowAll = gid >> 7;                              // e*2048 + k (128 threads/row)
    int n0 = (int)(gid & 127) * 8;
    const float4* g = (const float4*)(Wg + rowAll * HE + n0);
    const float4* u = (const float4*)(Wu + rowAll * HE + n0);
    float4 g0 = g[0], g1 = g[1], u0 = u[0], u1 = u[1];
    __align__(16) __half2 h[8];
    h[0] = __floats2half2_rn(g0.x, u0.x); h[1] = __floats2half2_rn(g0.y, u0.y);
    h[2] = __floats2half2_rn(g0.z, u0.z); h[3] = __floats2half2_rn(g0.w, u0.w);
    h[4] = __floats2half2_rn(g1.x, u1.x); h[5] = __floats2half2_rn(g1.y, u1.y);
    h[6] = __floats2half2_rn(g1.z, u1.z); h[7] = __floats2half2_rn(g1.w, u1.w);
    uint4* d = (uint4*)d_wguh + gid * 2;
    d[0] = *(uint4*)&h[0];
    d[1] = *(uint4*)&h[4];
}
__global__ __launch_bounds__(256) void conv_wd_kernel(const float* __restrict__ Wd) {
    size_t gid = (size_t)blockIdx.x * 256 + threadIdx.x;
    const float4* s = (const float4*)Wd + gid * 4;
    uint4* d = (uint4*)d_wdh + gid * 2;
    d[0] = pack8(s[0], s[1]);
    d[1] = pack8(s[2], s[3]);
}

// ============================================================================
// GEMM1: xh[perm] x wgu (interleaved) -> h = silu(g)*u (fp16)
// block 128 rows x 128 comb cols. grid (16, 32, 8). 64 chunks of k=32.
// cp.async 4-stage pipeline, 1 barrier per chunk.
// ============================================================================
__global__ __launch_bounds__(256, 2) void gemm1_kernel() {
    const int e = blockIdx.z;
    const int cnt = d_counts[e];
    const int row0 = blockIdx.y * 128;
    if (row0 >= cnt) return;
    const int off = d_offsets[e];
    const int bx = blockIdx.x;

    extern __shared__ __align__(16) char smem[];
    const uint32_t sb = smem_u32(smem);

    const int t = threadIdx.x, lane = t & 31, w = t >> 5;
    const int wm = w & 1, wn = w >> 1;

    // A: 128 rows x 64B; thread -> row t>>1, 32B seg (t&1)
    const int ar2 = t >> 1, ah = t & 1;
    int arr = row0 + ar2; if (arr >= cnt) arr = cnt - 1;
    const char* srcA = (const char*)(d_xh + (size_t)d_perm[off + arr] * D_HID) + ah * 32;
    const uint32_t dstA = sb + ar2 * A_ROWB + ah * 32;
    // B: 32 rows x 256B; thread -> row t>>3, 32B seg (t&7)
    const int bk = t >> 3, bs = t & 7;
    const char* srcB = (const char*)(d_wguh + ((size_t)e * D_HID + bk) * (2 * HE) + bx * 128 + bs * 16);
    const uint32_t dstB = sb + NSTAGE * SLOT_A + bk * B_ROWB + bs * 32;

    const uint32_t a_off = (((lane & 7) + ((lane >> 3) & 1) * 8) * A_ROWB) + (lane >> 4) * 16;
    const uint32_t b_off = (((lane & 7) + ((lane >> 3) & 1) * 8) * B_ROWB) + (lane >> 4) * 16;

    float acc[4][4][4] = {};

    const int NC = D_HID / 32;
#pragma unroll
    for (int s = 0; s < NSTAGE - 1; s++) {
        CPA16(dstA + s * SLOT_A, srcA + s * 64);
        CPA16(dstA + s * SLOT_A + 16, srcA + s * 64 + 16);
        CPA16(dstB + s * SLOT_B, srcB + (size_t)s * 32 * (2 * HE) * 2);
        CPA16(dstB + s * SLOT_B + 16, srcB + (size_t)s * 32 * (2 * HE) * 2 + 16);
        CP_COMMIT();
    }

    for (int kc = 0; kc < NC; kc++) {
        CP_WAIT(NSTAGE - 2);
        __syncthreads();
        const int kn = kc + NSTAGE - 1;
        if (kn < NC) {
            const int sl = kn & (NSTAGE - 1);
            CPA16(dstA + sl * SLOT_A, srcA + kn * 64);
            CPA16(dstA + sl * SLOT_A + 16, srcA + kn * 64 + 16);
            CPA16(dstB + sl * SLOT_B, srcB + (size_t)kn * 32 * (2 * HE) * 2);
            CPA16(dstB + sl * SLOT_B + 16, srcB + (size_t)kn * 32 * (2 * HE) * 2 + 16);
        }
        CP_COMMIT();
        const int cur = kc & (NSTAGE - 1);
        const uint32_t sAc = sb + cur * SLOT_A;
        const uint32_t sBc = sb + NSTAGE * SLOT_A + cur * SLOT_B;
#pragma unroll
        for (int ks = 0; ks < 2; ks++) {
            uint4 a[4]; uint2 b[4];
#pragma unroll
            for (int mi = 0; mi < 4; mi++)
                LDMX4(a[mi], sAc + (wm * 4 + mi) * (16 * A_ROWB) + ks * 32 + a_off);
#pragma unroll
            for (int j = 0; j < 2; j++) {
                uint32_t r0, r1, r2, r3;
                LDMX4T(r0, r1, r2, r3, sBc + ks * (16 * B_ROWB) + (wn * 4 + 2 * j) * 16 + b_off);
                b[2 * j].x = r0;     b[2 * j].y = r1;
                b[2 * j + 1].x = r2; b[2 * j + 1].y = r3;
            }
#pragma unroll
            for (int mi = 0; mi < 4; mi++)
#pragma unroll
                for (int ni = 0; ni < 4; ni++)
                    mma16(acc[mi][ni], a[mi], b[ni]);
        }
    }
    CP_WAIT(0);

    const int q = lane & 3;
#pragma unroll
    for (int mi = 0; mi < 4; mi++) {
        int r1 = row0 + wm * 64 + mi * 16 + (lane >> 2), r2 = r1 + 8;
#pragma unroll
        for (int ni = 0; ni < 4; ni++) {
            int hc = bx * 64 + wn * 16 + ni * 4 + q;
            if (r1 < cnt) {
                float g = acc[mi][ni][0], u = acc[mi][ni][1];
                d_hbufh[(size_t)(off + r1) * HE + hc] = __float2half_rn(g / (1.f + __expf(-g)) * u);
            }
            if (r2 < cnt) {
                float g = acc[mi][ni][2], u = acc[mi][ni][3];
                d_hbufh[(size_t)(off + r2) * HE + hc] = __float2half_rn(g / (1.f + __expf(-g)) * u);
            }
        }
    }
}

// ============================================================================
// GEMM2: h (fp16) x wdh -> out fp32, scatter via perm
// ============================================================================
__global__ __launch_bounds__(256, 2) void gemm2_kernel(float* __restrict__ out) {
    const int e = blockIdx.z;
    const int cnt = d_counts[e];
    const int row0 = blockIdx.y * 128;
    if (row0 >= cnt) return;
    const int off = d_offsets[e];
    const int bx = blockIdx.x;

    extern __shared__ __align__(16) char smem[];
    const uint32_t sb = smem_u32(smem);

    const int t = threadIdx.x, lane = t & 31, w = t >> 5;
    const int wm = w & 1, wn = w >> 1;

    const int ar2 = t >> 1, ah = t & 1;
    int hr = off + row0 + ar2; if (hr > T_TOKENS - 1) hr = T_TOKENS - 1;
    const char* srcA = (const char*)(d_hbufh + (size_t)hr * HE) + ah * 32;
    const uint32_t dstA = sb + ar2 * A_ROWB + ah * 32;

    const int bk = t >> 3, bs = t & 7;
    const char* srcB = (const char*)(d_wdh + ((size_t)e * HE + bk) * D_HID + bx * 128 + bs * 16);
    const uint32_t dstB = sb + NSTAGE * SLOT_A + bk * B_ROWB + bs * 32;

    const uint32_t a_off = (((lane & 7) + ((lane >> 3) & 1) * 8) * A_ROWB) + (lane >> 4) * 16;
    const uint32_t b_off = (((lane & 7) + ((lane >> 3) & 1) * 8) * B_ROWB) + (lane >> 4) * 16;

    float acc[4][4][4] = {};

    const int NC = HE / 32;
#pragma unroll
    for (int s = 0; s < NSTAGE - 1; s++) {
        CPA16(dstA + s * SLOT_A, srcA + s * 64);
        CPA16(dstA + s * SLOT_A + 16, srcA + s * 64 + 16);
        CPA16(dstB + s * SLOT_B, srcB + (size_t)s * 32 * D_HID * 2);
        CPA16(dstB + s * SLOT_B + 16, srcB + (size_t)s * 32 * D_HID * 2 + 16);
        CP_COMMIT();
    }

    for (int kc = 0; kc < NC; kc++) {
        CP_WAIT(NSTAGE - 2);
        __syncthreads();
        const int kn = kc + NSTAGE - 1;
        if (kn < NC) {
            const int sl = kn & (NSTAGE - 1);
            CPA16(dstA + sl * SLOT_A, srcA + kn * 64);
            CPA16(dstA + sl * SLOT_A + 16, srcA + kn * 64 + 16);
            CPA16(dstB + sl * SLOT_B, srcB + (size_t)kn * 32 * D_HID * 2);
            CPA16(dstB + sl * SLOT_B + 16, srcB + (size_t)kn * 32 * D_HID * 2 + 16);
        }
        CP_COMMIT();
        const int cur = kc & (NSTAGE - 1);
        const uint32_t sAc = sb + cur * SLOT_A;
        const uint32_t sBc = sb + NSTAGE * SLOT_A + cur * SLOT_B;
#pragma unroll
        for (int ks = 0; ks < 2; ks++) {
            uint4 a[4]; uint2 b[4];
#pragma unroll
            for (int mi = 0; mi < 4; mi++)
                LDMX4(a[mi], sAc + (wm * 4 + mi) * (16 * A_ROWB) + ks * 32 + a_off);
#pragma unroll
            for (int j = 0; j < 2; j++) {
                uint32_t r0, r1, r2, r3;
                LDMX4T(r0, r1, r2, r3, sBc + ks * (16 * B_ROWB) + (wn * 4 + 2 * j) * 16 + b_off);
                b[2 * j].x = r0;     b[2 * j].y = r1;
                b[2 * j + 1].x = r2; b[2 * j + 1].y = r3;
            }
#pragma unroll
            for (int mi = 0; mi < 4; mi++)
#pragma unroll
                for (int ni = 0; ni < 4; ni++)
                    mma16(acc[mi][ni], a[mi], b[ni]);
        }
    }
    CP_WAIT(0);

    const int q = lane & 3;
#pragma unroll
    for (int mi = 0; mi < 4; mi++) {
        int r1 = row0 + wm * 64 + mi * 16 + (lane >> 2), r2 = r1 + 8;
#pragma unroll
        for (int ni = 0; ni < 4; ni++) {
            int col = bx * 128 + wn * 32 + ni * 8 + 2 * q;
            if (r1 < cnt) {
                float2 v; v.x = acc[mi][ni][0]; v.y = acc[mi][ni][1];
                *(float2*)(out + (size_t)d_perm[off + r1] * D_HID + col) = v;
            }
            if (r2 < cnt) {
                float2 v; v.x = acc[mi][ni][2]; v.y = acc[mi][ni][3];
                *(float2*)(out + (size_t)d_perm[off + r2] * D_HID + col) = v;
            }
        }
    }
}

// ============================ launch (graph-forked streams) ============================
extern "C" void kernel_launch(void* const* d_in, const int* in_sizes, int n_in,
                              void* d_out, int out_size) {
    const float* x   = (const float*)d_in[0];
    const void*  tok = d_in[1];
    const float* Wg  = (const float*)d_in[2];
    const float* Wu  = (const float*)d_in[3];
    const float* Wd  = (const float*)d_in[4];
    float* out = (float*)d_out;

    static cudaStream_t s1 = nullptr;
    static cudaEvent_t ev0 = nullptr, evR = nullptr, evG = nullptr, evW = nullptr;
    if (!s1) {   // first call is the uncaptured correctness run: safe to create here
        cudaStreamCreateWithFlags(&s1, cudaStreamNonBlocking);
        cudaEventCreateWithFlags(&ev0, cudaEventDisableTiming);
        cudaEventCreateWithFlags(&evR, cudaEventDisableTiming);
        cudaEventCreateWithFlags(&evG, cudaEventDisableTiming);
        cudaEventCreateWithFlags(&evW, cudaEventDisableTiming);
        cudaFuncSetAttribute(gemm1_kernel, cudaFuncAttributeMaxDynamicSharedMemorySize, SMEM_TOT);
        cudaFuncSetAttribute(gemm2_kernel, cudaFuncAttributeMaxDynamicSharedMemorySize, SMEM_TOT);
    }

    // fork: route on s1, converts on main stream (concurrent)
    cudaEventRecord(ev0, 0);
    cudaStreamWaitEvent(s1, ev0, 0);
    route_kernel<<<1, 256, 0, s1>>>(tok);
    cudaEventRecord(evR, s1);

    conv_x_kernel<<<(T_TOKENS * D_HID / 16) / 256, 256>>>(x);
    conv_wgu_kernel<<<(NEXP * D_HID * 2 * HE / 16) / 256, 256>>>(Wg, Wu);

    // gemm1 needs route + conv_x + conv_wgu
    cudaStreamWaitEvent(0, evR, 0);
    cudaEventRecord(evG, 0);
    // conv_wd overlaps gemm1 on s1 (gemm2-only dependency)
    cudaStreamWaitEvent(s1, evG, 0);
    conv_wd_kernel<<<(NEXP * HE * D_HID / 16) / 256, 256, 0, s1>>>(Wd);
    cudaEventRecord(evW, s1);

    gemm1_kernel<<<dim3(HE / 64, T_TOKENS / 128, NEXP), 256, SMEM_TOT>>>();

    // gemm2 needs gemm1 (stream 0 order) + conv_wd
    cudaStreamWaitEvent(0, evW, 0);
    gemm2_kernel<<<dim3(D_HID / 128, T_TOKENS / 128, NEXP), 256, SMEM_TOT>>>(out);
}